// round 1
// baseline (speedup 1.0000x reference)
#include <cuda_runtime.h>
#include <stdint.h>

#define NMAX 50000
#define EMAX 800000

// ---------------- scratch (static __device__ — no runtime allocation) ----------------
__device__ float g_agg1[(size_t)NMAX * 128];
__device__ float g_agg2[(size_t)NMAX * 128];
__device__ float g_h1  [(size_t)NMAX * 128];
__device__ float g_xw  [(size_t)NMAX * 64];
__device__ float g_cnt [NMAX];
__device__ float g_dinv[NMAX];
__device__ int   g_src [EMAX];
__device__ int   g_dst [EMAX];
__device__ int   g_not64;

// vectorized non-returning global reduction (sm_90+)
__device__ __forceinline__ void red_add_v4(float* p, float a, float b, float c, float d) {
    asm volatile("red.global.add.v4.f32 [%0], {%1,%2,%3,%4};"
                 :: "l"(p), "f"(a), "f"(b), "f"(c), "f"(d) : "memory");
}

// ---------------- edge-index dtype detection + normalization ----------------
// If the buffer really is int64, the first E 64-bit words are the src row, all in [0,N).
// If it is int32 (JAX default x64-disabled), the first E 64-bit words cover the whole
// 2E-int32 buffer; some packed pair will exceed N. Deterministic given the input.
__global__ void detect_kernel(const long long* __restrict__ ei, int E, int N) {
    int i = blockIdx.x * blockDim.x + threadIdx.x;
    if (i >= E) return;
    unsigned long long v = (unsigned long long)ei[i];
    if (v >= (unsigned long long)N) g_not64 = 1;   // racy same-value store: fine
}

__global__ void convert_kernel(const void* __restrict__ ei, int E) {
    int i = blockIdx.x * blockDim.x + threadIdx.x;
    if (i >= E) return;
    if (g_not64) {
        const int* p = (const int*)ei;
        g_src[i] = p[i];
        g_dst[i] = p[E + i];
    } else {
        const long long* p = (const long long*)ei;
        g_src[i] = (int)p[i];
        g_dst[i] = (int)p[E + i];
    }
}

// ---------------- SAGE edge scatter: one warp per edge, 128 floats ----------------
template <bool COUNT>
__global__ void sage_edge_kernel(const float* __restrict__ feat, float* __restrict__ agg, int E) {
    int gw   = (blockIdx.x * blockDim.x + threadIdx.x) >> 5;
    int lane = threadIdx.x & 31;
    if (gw >= E) return;
    int s = g_src[gw];
    int d = g_dst[gw];
    float4 v = ((const float4*)(feat + (size_t)s * 128))[lane];
    red_add_v4(agg + (size_t)d * 128 + lane * 4, v.x, v.y, v.z, v.w);
    if (COUNT && lane == 0) atomicAdd(g_cnt + d, 1.0f);
}

// ---------------- GCN edge scatter: 16 lanes per edge, 64 floats ----------------
__global__ void gcn_edge_kernel(float* __restrict__ out, int E) {
    int t = blockIdx.x * blockDim.x + threadIdx.x;
    int e = t >> 4;
    int l = t & 15;
    if (e >= E) return;
    int s = g_src[e];
    int d = g_dst[e];
    float nrm = g_dinv[s] * g_dinv[d];
    float4 v = ((const float4*)(g_xw + (size_t)s * 64))[l];
    red_add_v4(out + (size_t)d * 64 + l * 4, v.x * nrm, v.y * nrm, v.z * nrm, v.w * nrm);
}

// ---------------- SAGE1 node: h1 = relu(mean1 @ W1l + b1l + x @ W1r) ----------------
// Weights in SMEM (128 KB), per-warp 4-row staging buffer, 4 rows x 4 cols per thread.
__global__ __launch_bounds__(512, 1)
void node1_kernel(const float* __restrict__ x,
                  const float* __restrict__ W1l,
                  const float* __restrict__ b1l,
                  const float* __restrict__ W1r, int N) {
    extern __shared__ float sm[];
    float* Wl    = sm;                 // 128*128
    float* Wr    = sm + 16384;         // 128*128
    float* rbase = sm + 32768;         // nw * 4 * 256
    for (int i = threadIdx.x; i < 16384; i += blockDim.x) { Wl[i] = W1l[i]; Wr[i] = W1r[i]; }
    __syncthreads();

    int warpId = threadIdx.x >> 5, lane = threadIdx.x & 31;
    int nw = blockDim.x >> 5;
    float* rb = rbase + warpId * 1024;
    float4 bv = ((const float4*)b1l)[lane];
    const float4* Wl4 = (const float4*)Wl;
    const float4* Wr4 = (const float4*)Wr;

    for (int base = (blockIdx.x * nw + warpId) * 4; base < N; base += gridDim.x * nw * 4) {
        #pragma unroll
        for (int r = 0; r < 4; r++) {
            int row = base + r;
            float4 av, xv;
            if (row < N) {
                float inv = 1.0f / fmaxf(g_cnt[row], 1.0f);
                av = ((const float4*)(g_agg1 + (size_t)row * 128))[lane];
                av.x *= inv; av.y *= inv; av.z *= inv; av.w *= inv;
                xv = ((const float4*)(x + (size_t)row * 128))[lane];
            } else {
                av = make_float4(0.f, 0.f, 0.f, 0.f); xv = av;
            }
            ((float4*)(rb + r * 256))[lane] = av;
            ((float4*)(rb + r * 256 + 128))[lane] = xv;
        }
        __syncwarp();

        float4 acc[4];
        #pragma unroll
        for (int r = 0; r < 4; r++) acc[r] = bv;

        #pragma unroll 4
        for (int k = 0; k < 128; k++) {
            float4 wl = Wl4[k * 32 + lane];
            float4 wr = Wr4[k * 32 + lane];
            #pragma unroll
            for (int r = 0; r < 4; r++) {
                float a = rb[r * 256 + k];
                float b = rb[r * 256 + 128 + k];
                acc[r].x += a * wl.x + b * wr.x;
                acc[r].y += a * wl.y + b * wr.y;
                acc[r].z += a * wl.z + b * wr.z;
                acc[r].w += a * wl.w + b * wr.w;
            }
        }

        #pragma unroll
        for (int r = 0; r < 4; r++) {
            int row = base + r;
            if (row < N) {
                float4 o = acc[r];
                o.x = fmaxf(o.x, 0.f); o.y = fmaxf(o.y, 0.f);
                o.z = fmaxf(o.z, 0.f); o.w = fmaxf(o.w, 0.f);
                ((float4*)(g_h1 + (size_t)row * 128))[lane] = o;
            }
        }
        __syncwarp();
    }
}

// ---------------- SAGE2 node + softmax + @Wg + GCN self-loop init of out ----------------
// t = mean2 @ W2l + b2l + h1 @ W2r ; s = softmax(t) ; xw = s @ Wg
// out[row] = xw*dinv^2 + bg  (edge terms added later by gcn_edge_kernel)
__global__ __launch_bounds__(512, 1)
void node2_kernel(const float* __restrict__ W2l, const float* __restrict__ b2l,
                  const float* __restrict__ W2r, const float* __restrict__ Wg,
                  const float* __restrict__ bg, float* __restrict__ out, int N) {
    extern __shared__ float sm[];
    int nw = blockDim.x >> 5;
    float* Wc    = sm;                       // 256*64  (W2l rows then W2r rows)
    float* Wgs   = sm + 16384;               // 64*64
    float* rbase = sm + 16384 + 4096;        // nw*4*256
    float* sbase = rbase + nw * 1024;        // nw*64

    for (int i = threadIdx.x; i < 8192; i += blockDim.x) { Wc[i] = W2l[i]; Wc[8192 + i] = W2r[i]; }
    for (int i = threadIdx.x; i < 4096; i += blockDim.x) { Wgs[i] = Wg[i]; }
    __syncthreads();

    int warpId = threadIdx.x >> 5, lane = threadIdx.x & 31;
    float* rb = rbase + warpId * 1024;
    float* sw = sbase + warpId * 64;
    float2 bv  = ((const float2*)b2l)[lane];
    float2 bgv = ((const float2*)bg)[lane];
    const float2* Wc2 = (const float2*)Wc;
    const float2* Wg2 = (const float2*)Wgs;

    for (int base = (blockIdx.x * nw + warpId) * 4; base < N; base += gridDim.x * nw * 4) {
        #pragma unroll
        for (int r = 0; r < 4; r++) {
            int row = base + r;
            float4 av, hv;
            if (row < N) {
                float inv = 1.0f / fmaxf(g_cnt[row], 1.0f);
                av = ((const float4*)(g_agg2 + (size_t)row * 128))[lane];
                av.x *= inv; av.y *= inv; av.z *= inv; av.w *= inv;
                hv = ((const float4*)(g_h1 + (size_t)row * 128))[lane];
            } else {
                av = make_float4(0.f, 0.f, 0.f, 0.f); hv = av;
            }
            ((float4*)(rb + r * 256))[lane] = av;
            ((float4*)(rb + r * 256 + 128))[lane] = hv;
        }
        __syncwarp();

        float2 acc[4];
        #pragma unroll
        for (int r = 0; r < 4; r++) acc[r] = bv;

        #pragma unroll 4
        for (int k = 0; k < 256; k++) {
            float2 w = Wc2[k * 32 + lane];
            #pragma unroll
            for (int r = 0; r < 4; r++) {
                float a = rb[r * 256 + k];
                acc[r].x += a * w.x;
                acc[r].y += a * w.y;
            }
        }

        #pragma unroll
        for (int r = 0; r < 4; r++) {
            int row = base + r;
            if (row >= N) continue;                    // uniform across warp
            float v0 = acc[r].x, v1 = acc[r].y;
            float m = fmaxf(v0, v1);
            #pragma unroll
            for (int o = 16; o; o >>= 1) m = fmaxf(m, __shfl_xor_sync(0xffffffffu, m, o));
            float e0 = __expf(v0 - m), e1 = __expf(v1 - m);
            float ssum = e0 + e1;
            #pragma unroll
            for (int o = 16; o; o >>= 1) ssum += __shfl_xor_sync(0xffffffffu, ssum, o);
            float inv = 1.0f / ssum;
            sw[lane * 2]     = e0 * inv;
            sw[lane * 2 + 1] = e1 * inv;
            __syncwarp();

            float2 a2 = make_float2(0.f, 0.f);
            #pragma unroll 4
            for (int k = 0; k < 64; k++) {
                float s = sw[k];
                float2 g = Wg2[k * 32 + lane];
                a2.x += s * g.x;
                a2.y += s * g.y;
            }
            __syncwarp();

            float dv = rsqrtf(g_cnt[row] + 1.0f);
            ((float2*)(g_xw + (size_t)row * 64))[lane] = a2;
            float d2 = dv * dv;
            float2 o2 = make_float2(a2.x * d2 + bgv.x, a2.y * d2 + bgv.y);
            ((float2*)(out + (size_t)row * 64))[lane] = o2;
            if (lane == 0) g_dinv[row] = dv;
        }
    }
}

// ---------------- host launcher ----------------
extern "C" void kernel_launch(void* const* d_in, const int* in_sizes, int n_in,
                              void* d_out, int out_size) {
    const float* x   = (const float*)d_in[0];
    const void*  ei  = d_in[1];
    const float* W1l = (const float*)d_in[2];
    const float* b1l = (const float*)d_in[3];
    const float* W1r = (const float*)d_in[4];
    const float* W2l = (const float*)d_in[5];
    const float* b2l = (const float*)d_in[6];
    const float* W2r = (const float*)d_in[7];
    const float* Wg  = (const float*)d_in[8];
    const float* bg  = (const float*)d_in[9];
    float* out = (float*)d_out;

    int N = in_sizes[0] / 128;
    int E = in_sizes[1] / 2;

    void *p_agg1, *p_agg2, *p_cnt, *p_flag, *p_h1;
    cudaGetSymbolAddress(&p_agg1, g_agg1);
    cudaGetSymbolAddress(&p_agg2, g_agg2);
    cudaGetSymbolAddress(&p_cnt,  g_cnt);
    cudaGetSymbolAddress(&p_flag, g_not64);
    cudaGetSymbolAddress(&p_h1,   g_h1);

    cudaMemsetAsync(p_agg1, 0, (size_t)N * 128 * sizeof(float));
    cudaMemsetAsync(p_agg2, 0, (size_t)N * 128 * sizeof(float));
    cudaMemsetAsync(p_cnt,  0, (size_t)N * sizeof(float));
    cudaMemsetAsync(p_flag, 0, sizeof(int));

    // edge-index normalization
    int eb = (E + 255) / 256;
    detect_kernel<<<eb, 256>>>((const long long*)ei, E, N);
    convert_kernel<<<eb, 256>>>(ei, E);

    // SAGE1
    long long t1 = (long long)E * 32;
    sage_edge_kernel<true><<<(unsigned)((t1 + 255) / 256), 256>>>(x, (float*)p_agg1, E);
    cudaFuncSetAttribute(node1_kernel, cudaFuncAttributeMaxDynamicSharedMemorySize, 196608);
    node1_kernel<<<148, 512, 196608>>>(x, W1l, b1l, W1r, N);

    // SAGE2 (+softmax +@Wg +self-loop init)
    sage_edge_kernel<false><<<(unsigned)((t1 + 255) / 256), 256>>>((const float*)p_h1, (float*)p_agg2, E);
    cudaFuncSetAttribute(node2_kernel, cudaFuncAttributeMaxDynamicSharedMemorySize, 152064);
    node2_kernel<<<148, 512, 152064>>>(W2l, b2l, W2r, Wg, bg, out, N);

    // GCN edge accumulation
    long long t2 = (long long)E * 16;
    gcn_edge_kernel<<<(unsigned)((t2 + 255) / 256), 256>>>(out, E);
}

// round 4
// speedup vs baseline: 1.0376x; 1.0376x over previous
#include <cuda_runtime.h>
#include <stdint.h>

#define NMAX 50000
#define EMAX 800000
#define SCAN_BS 512

// ---------------- scratch (static __device__ — no runtime allocation) ----------------
__device__ float g_h1  [(size_t)NMAX * 128];
__device__ float g_xw  [(size_t)NMAX * 64];
__device__ float g_dinv[NMAX];
__device__ int   g_src [EMAX];
__device__ int   g_dst [EMAX];
__device__ int   g_csrc[EMAX];
__device__ int   g_deg [NMAX];
__device__ int   g_fill[NMAX];
__device__ int   g_rowptr[NMAX + 1];
__device__ int   g_bsum[128];
__device__ int   g_not64;

// ---------------- edge-index dtype detection + normalization ----------------
__global__ void detect_kernel(const long long* __restrict__ ei, int E, int N) {
    int i = blockIdx.x * blockDim.x + threadIdx.x;
    if (i >= E) return;
    unsigned long long v = (unsigned long long)ei[i];
    if (v >= (unsigned long long)N) g_not64 = 1;   // racy same-value store: fine
}

__global__ void convert_kernel(const void* __restrict__ ei, int E) {
    int i = blockIdx.x * blockDim.x + threadIdx.x;
    if (i >= E) return;
    if (g_not64) {
        const int* p = (const int*)ei;
        g_src[i] = p[i];
        g_dst[i] = p[E + i];
    } else {
        const long long* p = (const long long*)ei;
        g_src[i] = (int)p[i];
        g_dst[i] = (int)p[E + i];
    }
}

// ---------------- CSR build ----------------
__global__ void hist_kernel(int E) {
    int i = blockIdx.x * blockDim.x + threadIdx.x;
    if (i >= E) return;
    atomicAdd(&g_deg[g_dst[i]], 1);
}

__global__ void scan_block_sums(int N) {
    __shared__ int sh[SCAN_BS];
    int i = blockIdx.x * SCAN_BS + threadIdx.x;
    sh[threadIdx.x] = (i < N) ? g_deg[i] : 0;
    __syncthreads();
    for (int o = SCAN_BS / 2; o > 0; o >>= 1) {
        if (threadIdx.x < o) sh[threadIdx.x] += sh[threadIdx.x + o];
        __syncthreads();
    }
    if (threadIdx.x == 0) g_bsum[blockIdx.x] = sh[0];
}

__global__ void scan_bsum(int nb) {   // single block, 128 threads, nb <= 128
    __shared__ int sh[128];
    int v = (threadIdx.x < nb) ? g_bsum[threadIdx.x] : 0;
    sh[threadIdx.x] = v;
    __syncthreads();
    for (int o = 1; o < 128; o <<= 1) {
        int t = (threadIdx.x >= o) ? sh[threadIdx.x - o] : 0;
        __syncthreads();
        sh[threadIdx.x] += t;
        __syncthreads();
    }
    if (threadIdx.x < nb) g_bsum[threadIdx.x] = sh[threadIdx.x] - v;  // exclusive
}

__global__ void scan_final(int N, int E) {
    __shared__ int sh[SCAN_BS];
    int i = blockIdx.x * SCAN_BS + threadIdx.x;
    int d = (i < N) ? g_deg[i] : 0;
    sh[threadIdx.x] = d;
    __syncthreads();
    for (int o = 1; o < SCAN_BS; o <<= 1) {
        int t = (threadIdx.x >= o) ? sh[threadIdx.x - o] : 0;
        __syncthreads();
        sh[threadIdx.x] += t;
        __syncthreads();
    }
    if (i < N) {
        g_rowptr[i] = g_bsum[blockIdx.x] + sh[threadIdx.x] - d;
        g_dinv[i]   = rsqrtf((float)d + 1.0f);
    }
    if (i == 0) g_rowptr[N] = E;
}

__global__ void fill_kernel(int E) {
    int i = blockIdx.x * blockDim.x + threadIdx.x;
    if (i >= E) return;
    int d = g_dst[i];
    int pos = g_rowptr[d] + atomicAdd(&g_fill[d], 1);
    g_csrc[pos] = g_src[i];
}

// ---------------- warp-uniform neighbor mean gather (128 floats, float4/lane) ----------------
__device__ __forceinline__ float4 gather_mean128(const float* __restrict__ feat,
                                                 int start, int end, int lane) {
    float4 a0 = make_float4(0.f, 0.f, 0.f, 0.f);
    float4 a1 = make_float4(0.f, 0.f, 0.f, 0.f);
    for (int eb = start; eb < end; eb += 32) {
        int m = end - eb; if (m > 32) m = 32;
        int sl = (lane < m) ? g_csrc[eb + lane] : 0;
        for (int k = 0; k < m; k += 2) {
            int s0 = __shfl_sync(0xffffffffu, sl, k);
            float4 v0 = ((const float4*)(feat + (size_t)s0 * 128))[lane];
            a0.x += v0.x; a0.y += v0.y; a0.z += v0.z; a0.w += v0.w;
            if (k + 1 < m) {
                int s1 = __shfl_sync(0xffffffffu, sl, k + 1);
                float4 v1 = ((const float4*)(feat + (size_t)s1 * 128))[lane];
                a1.x += v1.x; a1.y += v1.y; a1.z += v1.z; a1.w += v1.w;
            }
        }
    }
    float inv = 1.0f / fmaxf((float)(end - start), 1.0f);
    return make_float4((a0.x + a1.x) * inv, (a0.y + a1.y) * inv,
                       (a0.z + a1.z) * inv, (a0.w + a1.w) * inv);
}

// ---------------- SAGE1 node (fused gather): h1 = relu(mean1 @ W1l + b1l + x @ W1r) ----------------
__global__ __launch_bounds__(512, 1)
void node1_kernel(const float* __restrict__ x,
                  const float* __restrict__ W1l,
                  const float* __restrict__ b1l,
                  const float* __restrict__ W1r, int N) {
    extern __shared__ float sm[];
    float* Wl    = sm;                 // 128*128
    float* Wr    = sm + 16384;         // 128*128
    float* rbase = sm + 32768;         // nw * 4 * 256
    for (int i = threadIdx.x; i < 16384; i += blockDim.x) { Wl[i] = W1l[i]; Wr[i] = W1r[i]; }
    __syncthreads();

    int warpId = threadIdx.x >> 5, lane = threadIdx.x & 31;
    int nw = blockDim.x >> 5;
    float* rb = rbase + warpId * 1024;
    float4 bv = ((const float4*)b1l)[lane];
    const float4* Wl4 = (const float4*)Wl;
    const float4* Wr4 = (const float4*)Wr;

    for (int base = (blockIdx.x * nw + warpId) * 4; base < N; base += gridDim.x * nw * 4) {
        // coalesced rowptr fetch: lanes 0..4 read the 5 boundaries for 4 rows
        int rp = 0;
        if (lane <= 4 && base + lane <= N) rp = g_rowptr[min(base + lane, N)];
        #pragma unroll
        for (int r = 0; r < 4; r++) {
            int row = base + r;
            int st = __shfl_sync(0xffffffffu, rp, r);
            int en = __shfl_sync(0xffffffffu, rp, r + 1);
            float4 av, xv;
            if (row < N) {
                av = gather_mean128(x, st, en, lane);
                xv = ((const float4*)(x + (size_t)row * 128))[lane];
            } else {
                av = make_float4(0.f, 0.f, 0.f, 0.f); xv = av;
            }
            ((float4*)(rb + r * 256))[lane] = av;
            ((float4*)(rb + r * 256 + 128))[lane] = xv;
        }
        __syncwarp();

        float4 acc[4];
        #pragma unroll
        for (int r = 0; r < 4; r++) acc[r] = bv;

        #pragma unroll 4
        for (int k = 0; k < 128; k++) {
            float4 wl = Wl4[k * 32 + lane];
            float4 wr = Wr4[k * 32 + lane];
            #pragma unroll
            for (int r = 0; r < 4; r++) {
                float a = rb[r * 256 + k];
                float b = rb[r * 256 + 128 + k];
                acc[r].x += a * wl.x + b * wr.x;
                acc[r].y += a * wl.y + b * wr.y;
                acc[r].z += a * wl.z + b * wr.z;
                acc[r].w += a * wl.w + b * wr.w;
            }
        }

        #pragma unroll
        for (int r = 0; r < 4; r++) {
            int row = base + r;
            if (row < N) {
                float4 o = acc[r];
                o.x = fmaxf(o.x, 0.f); o.y = fmaxf(o.y, 0.f);
                o.z = fmaxf(o.z, 0.f); o.w = fmaxf(o.w, 0.f);
                ((float4*)(g_h1 + (size_t)row * 128))[lane] = o;
            }
        }
        __syncwarp();
    }
}

// ---------------- SAGE2 node (fused gather) + softmax + @Wg + GCN self-loop init ----------------
__global__ __launch_bounds__(512, 1)
void node2_kernel(const float* __restrict__ W2l, const float* __restrict__ b2l,
                  const float* __restrict__ W2r, const float* __restrict__ Wg,
                  const float* __restrict__ bg, float* __restrict__ out, int N) {
    extern __shared__ float sm[];
    int nw = blockDim.x >> 5;
    float* Wc    = sm;                       // 256*64
    float* Wgs   = sm + 16384;               // 64*64
    float* rbase = sm + 16384 + 4096;        // nw*4*256
    float* sbase = rbase + nw * 1024;        // nw*64

    for (int i = threadIdx.x; i < 8192; i += blockDim.x) { Wc[i] = W2l[i]; Wc[8192 + i] = W2r[i]; }
    for (int i = threadIdx.x; i < 4096; i += blockDim.x) { Wgs[i] = Wg[i]; }
    __syncthreads();

    int warpId = threadIdx.x >> 5, lane = threadIdx.x & 31;
    float* rb = rbase + warpId * 1024;
    float* sw = sbase + warpId * 64;
    float2 bv  = ((const float2*)b2l)[lane];
    float2 bgv = ((const float2*)bg)[lane];
    const float2* Wc2 = (const float2*)Wc;
    const float2* Wg2 = (const float2*)Wgs;

    for (int base = (blockIdx.x * nw + warpId) * 4; base < N; base += gridDim.x * nw * 4) {
        int rp = 0;
        if (lane <= 4 && base + lane <= N) rp = g_rowptr[min(base + lane, N)];
        #pragma unroll
        for (int r = 0; r < 4; r++) {
            int row = base + r;
            int st = __shfl_sync(0xffffffffu, rp, r);
            int en = __shfl_sync(0xffffffffu, rp, r + 1);
            float4 av, hv;
            if (row < N) {
                av = gather_mean128(g_h1, st, en, lane);
                hv = ((const float4*)(g_h1 + (size_t)row * 128))[lane];
            } else {
                av = make_float4(0.f, 0.f, 0.f, 0.f); hv = av;
            }
            ((float4*)(rb + r * 256))[lane] = av;
            ((float4*)(rb + r * 256 + 128))[lane] = hv;
        }
        __syncwarp();

        float2 acc[4];
        #pragma unroll
        for (int r = 0; r < 4; r++) acc[r] = bv;

        #pragma unroll 4
        for (int k = 0; k < 256; k++) {
            float2 w = Wc2[k * 32 + lane];
            #pragma unroll
            for (int r = 0; r < 4; r++) {
                float a = rb[r * 256 + k];
                acc[r].x += a * w.x;
                acc[r].y += a * w.y;
            }
        }

        #pragma unroll
        for (int r = 0; r < 4; r++) {
            int row = base + r;
            if (row >= N) continue;                    // uniform across warp
            float v0 = acc[r].x, v1 = acc[r].y;
            float m = fmaxf(v0, v1);
            #pragma unroll
            for (int o = 16; o; o >>= 1) m = fmaxf(m, __shfl_xor_sync(0xffffffffu, m, o));
            float e0 = __expf(v0 - m), e1 = __expf(v1 - m);
            float ssum = e0 + e1;
            #pragma unroll
            for (int o = 16; o; o >>= 1) ssum += __shfl_xor_sync(0xffffffffu, ssum, o);
            float inv = 1.0f / ssum;
            sw[lane * 2]     = e0 * inv;
            sw[lane * 2 + 1] = e1 * inv;
            __syncwarp();

            float2 a2 = make_float2(0.f, 0.f);
            #pragma unroll 4
            for (int k = 0; k < 64; k++) {
                float s = sw[k];
                float2 g = Wg2[k * 32 + lane];
                a2.x += s * g.x;
                a2.y += s * g.y;
            }
            __syncwarp();

            float dv = g_dinv[row];
            ((float2*)(g_xw + (size_t)row * 64))[lane] = a2;
            float d2 = dv * dv;
            float2 o2 = make_float2(a2.x * d2 + bgv.x, a2.y * d2 + bgv.y);
            ((float2*)(out + (size_t)row * 64))[lane] = o2;
        }
    }
}

// ---------------- GCN: warp-per-node gather, non-atomic accumulate into out ----------------
__global__ void gcn_gather_kernel(float* __restrict__ out, int N) {
    int node = (blockIdx.x * blockDim.x + threadIdx.x) >> 5;
    int lane = threadIdx.x & 31;
    if (node >= N) return;
    int start = g_rowptr[node], end = g_rowptr[node + 1];
    float2 a0 = make_float2(0.f, 0.f), a1 = make_float2(0.f, 0.f);
    for (int eb = start; eb < end; eb += 32) {
        int m = end - eb; if (m > 32) m = 32;
        int sl = 0; float wl = 0.f;
        if (lane < m) { sl = g_csrc[eb + lane]; wl = g_dinv[sl]; }
        for (int k = 0; k < m; k += 2) {
            int   s0 = __shfl_sync(0xffffffffu, sl, k);
            float w0 = __shfl_sync(0xffffffffu, wl, k);
            float2 v0 = ((const float2*)(g_xw + (size_t)s0 * 64))[lane];
            a0.x += v0.x * w0; a0.y += v0.y * w0;
            if (k + 1 < m) {
                int   s1 = __shfl_sync(0xffffffffu, sl, k + 1);
                float w1 = __shfl_sync(0xffffffffu, wl, k + 1);
                float2 v1 = ((const float2*)(g_xw + (size_t)s1 * 64))[lane];
                a1.x += v1.x * w1; a1.y += v1.y * w1;
            }
        }
    }
    float di = g_dinv[node];
    float2* po = (float2*)(out + (size_t)node * 64) + lane;
    float2 cur = *po;
    cur.x += di * (a0.x + a1.x);
    cur.y += di * (a0.y + a1.y);
    *po = cur;
}

// ---------------- host launcher ----------------
extern "C" void kernel_launch(void* const* d_in, const int* in_sizes, int n_in,
                              void* d_out, int out_size) {
    const float* x   = (const float*)d_in[0];
    const void*  ei  = d_in[1];
    const float* W1l = (const float*)d_in[2];
    const float* b1l = (const float*)d_in[3];
    const float* W1r = (const float*)d_in[4];
    const float* W2l = (const float*)d_in[5];
    const float* b2l = (const float*)d_in[6];
    const float* W2r = (const float*)d_in[7];
    const float* Wg  = (const float*)d_in[8];
    const float* bg  = (const float*)d_in[9];
    float* out = (float*)d_out;

    int N = in_sizes[0] / 128;
    int E = in_sizes[1] / 2;

    void *p_deg, *p_fill, *p_flag;
    cudaGetSymbolAddress(&p_deg,  g_deg);
    cudaGetSymbolAddress(&p_fill, g_fill);
    cudaGetSymbolAddress(&p_flag, g_not64);

    cudaMemsetAsync(p_deg,  0, (size_t)N * sizeof(int));
    cudaMemsetAsync(p_fill, 0, (size_t)N * sizeof(int));
    cudaMemsetAsync(p_flag, 0, sizeof(int));

    // edge-index normalization
    int eb = (E + 255) / 256;
    detect_kernel<<<eb, 256>>>((const long long*)ei, E, N);
    convert_kernel<<<eb, 256>>>(ei, E);

    // CSR build (by dst)
    int nb = (N + SCAN_BS - 1) / SCAN_BS;
    hist_kernel<<<eb, 256>>>(E);
    scan_block_sums<<<nb, SCAN_BS>>>(N);
    scan_bsum<<<1, 128>>>(nb);
    scan_final<<<nb, SCAN_BS>>>(N, E);
    fill_kernel<<<eb, 256>>>(E);

    // SAGE1 (gather fused)
    cudaFuncSetAttribute(node1_kernel, cudaFuncAttributeMaxDynamicSharedMemorySize, 196608);
    node1_kernel<<<148, 512, 196608>>>(x, W1l, b1l, W1r, N);

    // SAGE2 (gather fused, +softmax +@Wg +self-loop init)
    cudaFuncSetAttribute(node2_kernel, cudaFuncAttributeMaxDynamicSharedMemorySize, 152064);
    node2_kernel<<<148, 512, 152064>>>(W2l, b2l, W2r, Wg, bg, out, N);

    // GCN edge accumulation (gather, non-atomic)
    int gb = (N * 32 + 255) / 256;
    gcn_gather_kernel<<<gb, 256>>>(out, N);
}

// round 5
// speedup vs baseline: 1.1100x; 1.0698x over previous
#include <cuda_runtime.h>
#include <stdint.h>

#define NMAX 50000
#define EMAX 800000
#define SCAN_BS 512

// ---------------- scratch (static __device__ — no runtime allocation) ----------------
__device__ float g_h1  [(size_t)NMAX * 128];
__device__ float g_xw  [(size_t)NMAX * 64];
__device__ float g_dinv[NMAX];
__device__ int   g_src [EMAX];
__device__ int   g_dst [EMAX];
__device__ int   g_csrc[EMAX];
__device__ int   g_deg [NMAX];
__device__ int   g_fill[NMAX];
__device__ int   g_rowptr[NMAX + 1];
__device__ int   g_bsum[128];
__device__ int   g_not64;

// ---------------- packed f32x2 helpers (FFMA2 — ptxas never emits this from C++) ----------
__device__ __forceinline__ void ffma2(unsigned long long& d, unsigned long long a, unsigned long long b) {
    asm("fma.rn.f32x2 %0, %1, %2, %0;" : "+l"(d) : "l"(a), "l"(b));
}
__device__ __forceinline__ unsigned long long pack_dup(float v) {
    unsigned long long r;
    asm("mov.b64 %0, {%1, %1};" : "=l"(r) : "f"(v));
    return r;
}
__device__ __forceinline__ unsigned long long pack_pair(float lo, float hi) {
    unsigned long long r;
    asm("mov.b64 %0, {%1, %2};" : "=l"(r) : "f"(lo), "f"(hi));
    return r;
}
__device__ __forceinline__ float2 unpack2(unsigned long long v) {
    float2 f;
    asm("mov.b64 {%0, %1}, %2;" : "=f"(f.x), "=f"(f.y) : "l"(v));
    return f;
}

// ---------------- edge-index dtype detection + normalization (+degree histogram) ----------
__global__ void detect_kernel(const long long* __restrict__ ei, int E, int N) {
    int i = blockIdx.x * blockDim.x + threadIdx.x;
    if (i >= E) return;
    unsigned long long v = (unsigned long long)ei[i];
    if (v >= (unsigned long long)N) g_not64 = 1;   // racy same-value store: fine
}

__global__ void convert_kernel(const void* __restrict__ ei, int E) {
    int i = blockIdx.x * blockDim.x + threadIdx.x;
    if (i >= E) return;
    int s, d;
    if (g_not64) {
        const int* p = (const int*)ei;
        s = p[i]; d = p[E + i];
    } else {
        const long long* p = (const long long*)ei;
        s = (int)p[i]; d = (int)p[E + i];
    }
    g_src[i] = s;
    g_dst[i] = d;
    atomicAdd(&g_deg[d], 1);
}

// ---------------- CSR build ----------------
__global__ void scan_block_sums(int N) {
    __shared__ int sh[SCAN_BS];
    int i = blockIdx.x * SCAN_BS + threadIdx.x;
    sh[threadIdx.x] = (i < N) ? g_deg[i] : 0;
    __syncthreads();
    for (int o = SCAN_BS / 2; o > 0; o >>= 1) {
        if (threadIdx.x < o) sh[threadIdx.x] += sh[threadIdx.x + o];
        __syncthreads();
    }
    if (threadIdx.x == 0) g_bsum[blockIdx.x] = sh[0];
}

__global__ void scan_bsum(int nb) {   // single block, 128 threads, nb <= 128
    __shared__ int sh[128];
    int v = (threadIdx.x < nb) ? g_bsum[threadIdx.x] : 0;
    sh[threadIdx.x] = v;
    __syncthreads();
    for (int o = 1; o < 128; o <<= 1) {
        int t = (threadIdx.x >= o) ? sh[threadIdx.x - o] : 0;
        __syncthreads();
        sh[threadIdx.x] += t;
        __syncthreads();
    }
    if (threadIdx.x < nb) g_bsum[threadIdx.x] = sh[threadIdx.x] - v;  // exclusive
}

__global__ void scan_final(int N, int E) {
    __shared__ int sh[SCAN_BS];
    int i = blockIdx.x * SCAN_BS + threadIdx.x;
    int d = (i < N) ? g_deg[i] : 0;
    sh[threadIdx.x] = d;
    __syncthreads();
    for (int o = 1; o < SCAN_BS; o <<= 1) {
        int t = (threadIdx.x >= o) ? sh[threadIdx.x - o] : 0;
        __syncthreads();
        sh[threadIdx.x] += t;
        __syncthreads();
    }
    if (i < N) {
        g_rowptr[i] = g_bsum[blockIdx.x] + sh[threadIdx.x] - d;
        g_dinv[i]   = rsqrtf((float)d + 1.0f);
    }
    if (i == 0) g_rowptr[N] = E;
}

__global__ void fill_kernel(int E) {
    int i = blockIdx.x * blockDim.x + threadIdx.x;
    if (i >= E) return;
    int d = g_dst[i];
    int pos = g_rowptr[d] + atomicAdd(&g_fill[d], 1);
    g_csrc[pos] = g_src[i];
}

// ---------------- warp-uniform neighbor mean gather (128 floats, MLP=4) ----------------
__device__ __forceinline__ float4 gather_mean128(const float* __restrict__ feat,
                                                 int start, int end, int lane) {
    float4 a0 = make_float4(0.f, 0.f, 0.f, 0.f);
    float4 a1 = make_float4(0.f, 0.f, 0.f, 0.f);
    float4 a2 = make_float4(0.f, 0.f, 0.f, 0.f);
    float4 a3 = make_float4(0.f, 0.f, 0.f, 0.f);
    for (int eb = start; eb < end; eb += 32) {
        int m = end - eb; if (m > 32) m = 32;
        int sl = (lane < m) ? g_csrc[eb + lane] : 0;
        for (int k = 0; k < m; k += 4) {
            int s0 = __shfl_sync(0xffffffffu, sl, k);
            float4 v0 = ((const float4*)(feat + (size_t)s0 * 128))[lane];
            a0.x += v0.x; a0.y += v0.y; a0.z += v0.z; a0.w += v0.w;
            if (k + 1 < m) {
                int s1 = __shfl_sync(0xffffffffu, sl, k + 1);
                float4 v1 = ((const float4*)(feat + (size_t)s1 * 128))[lane];
                a1.x += v1.x; a1.y += v1.y; a1.z += v1.z; a1.w += v1.w;
            }
            if (k + 2 < m) {
                int s2 = __shfl_sync(0xffffffffu, sl, k + 2);
                float4 v2 = ((const float4*)(feat + (size_t)s2 * 128))[lane];
                a2.x += v2.x; a2.y += v2.y; a2.z += v2.z; a2.w += v2.w;
            }
            if (k + 3 < m) {
                int s3 = __shfl_sync(0xffffffffu, sl, k + 3);
                float4 v3 = ((const float4*)(feat + (size_t)s3 * 128))[lane];
                a3.x += v3.x; a3.y += v3.y; a3.z += v3.z; a3.w += v3.w;
            }
        }
    }
    float inv = 1.0f / fmaxf((float)(end - start), 1.0f);
    return make_float4((a0.x + a1.x + a2.x + a3.x) * inv,
                       (a0.y + a1.y + a2.y + a3.y) * inv,
                       (a0.z + a1.z + a2.z + a3.z) * inv,
                       (a0.w + a1.w + a2.w + a3.w) * inv);
}

// ---------------- SAGE1 node (fused gather, FFMA2 GEMM) ----------------
// h1 = relu(mean1 @ W1l + b1l + x @ W1r)
__global__ __launch_bounds__(512, 1)
void node1_kernel(const float* __restrict__ x,
                  const float* __restrict__ W1l,
                  const float* __restrict__ b1l,
                  const float* __restrict__ W1r, int N) {
    extern __shared__ float sm[];
    float* Wl    = sm;                 // 128*128
    float* Wr    = sm + 16384;         // 128*128
    float* rbase = sm + 32768;         // nw * 4 * 256
    for (int i = threadIdx.x; i < 16384; i += blockDim.x) { Wl[i] = W1l[i]; Wr[i] = W1r[i]; }
    __syncthreads();

    int warpId = threadIdx.x >> 5, lane = threadIdx.x & 31;
    int nw = blockDim.x >> 5;
    float* rb = rbase + warpId * 1024;
    float4 bv = ((const float4*)b1l)[lane];
    unsigned long long bv01 = pack_pair(bv.x, bv.y);
    unsigned long long bv23 = pack_pair(bv.z, bv.w);
    const ulonglong2* Wl2 = (const ulonglong2*)Wl;   // [k][lane] as 2x f32x2
    const ulonglong2* Wr2 = (const ulonglong2*)Wr;

    for (int base = (blockIdx.x * nw + warpId) * 4; base < N; base += gridDim.x * nw * 4) {
        int rp = 0;
        if (lane <= 4 && base + lane <= N) rp = g_rowptr[min(base + lane, N)];
        #pragma unroll
        for (int r = 0; r < 4; r++) {
            int row = base + r;
            int st = __shfl_sync(0xffffffffu, rp, r);
            int en = __shfl_sync(0xffffffffu, rp, r + 1);
            float4 av, xv;
            if (row < N) {
                av = gather_mean128(x, st, en, lane);
                xv = ((const float4*)(x + (size_t)row * 128))[lane];
            } else {
                av = make_float4(0.f, 0.f, 0.f, 0.f); xv = av;
            }
            ((float4*)(rb + r * 256))[lane] = av;
            ((float4*)(rb + r * 256 + 128))[lane] = xv;
        }
        __syncwarp();

        unsigned long long acc01[4], acc23[4];
        #pragma unroll
        for (int r = 0; r < 4; r++) { acc01[r] = bv01; acc23[r] = bv23; }

        #pragma unroll 4
        for (int k = 0; k < 128; k++) {
            ulonglong2 wl = Wl2[k * 32 + lane];
            ulonglong2 wr = Wr2[k * 32 + lane];
            #pragma unroll
            for (int r = 0; r < 4; r++) {
                unsigned long long aa = pack_dup(rb[r * 256 + k]);
                unsigned long long bb = pack_dup(rb[r * 256 + 128 + k]);
                ffma2(acc01[r], aa, wl.x);
                ffma2(acc23[r], aa, wl.y);
                ffma2(acc01[r], bb, wr.x);
                ffma2(acc23[r], bb, wr.y);
            }
        }

        #pragma unroll
        for (int r = 0; r < 4; r++) {
            int row = base + r;
            if (row < N) {
                float2 lo = unpack2(acc01[r]);
                float2 hi = unpack2(acc23[r]);
                float4 o = make_float4(fmaxf(lo.x, 0.f), fmaxf(lo.y, 0.f),
                                       fmaxf(hi.x, 0.f), fmaxf(hi.y, 0.f));
                ((float4*)(g_h1 + (size_t)row * 128))[lane] = o;
            }
        }
        __syncwarp();
    }
}

// ---------------- SAGE2 node (fused gather, FFMA2) + softmax + @Wg + GCN self-loop init ----
__global__ __launch_bounds__(512, 1)
void node2_kernel(const float* __restrict__ W2l, const float* __restrict__ b2l,
                  const float* __restrict__ W2r, const float* __restrict__ Wg,
                  const float* __restrict__ bg, float* __restrict__ out, int N) {
    extern __shared__ float sm[];
    int nw = blockDim.x >> 5;
    float* Wc    = sm;                       // 256*64  (W2l rows then W2r rows)
    float* Wgs   = sm + 16384;               // 64*64
    float* rbase = sm + 16384 + 4096;        // nw*4*256
    float* sbase = rbase + nw * 1024;        // nw*64

    for (int i = threadIdx.x; i < 8192; i += blockDim.x) { Wc[i] = W2l[i]; Wc[8192 + i] = W2r[i]; }
    for (int i = threadIdx.x; i < 4096; i += blockDim.x) { Wgs[i] = Wg[i]; }
    __syncthreads();

    int warpId = threadIdx.x >> 5, lane = threadIdx.x & 31;
    float* rb = rbase + warpId * 1024;
    float* sw = sbase + warpId * 64;
    float2 bv  = ((const float2*)b2l)[lane];
    float2 bgv = ((const float2*)bg)[lane];
    unsigned long long bvp = pack_pair(bv.x, bv.y);
    const unsigned long long* Wcp = (const unsigned long long*)Wc;   // [k][lane] f32x2
    const unsigned long long* Wgp = (const unsigned long long*)Wgs;

    for (int base = (blockIdx.x * nw + warpId) * 4; base < N; base += gridDim.x * nw * 4) {
        int rp = 0;
        if (lane <= 4 && base + lane <= N) rp = g_rowptr[min(base + lane, N)];
        #pragma unroll
        for (int r = 0; r < 4; r++) {
            int row = base + r;
            int st = __shfl_sync(0xffffffffu, rp, r);
            int en = __shfl_sync(0xffffffffu, rp, r + 1);
            float4 av, hv;
            if (row < N) {
                av = gather_mean128(g_h1, st, en, lane);
                hv = ((const float4*)(g_h1 + (size_t)row * 128))[lane];
            } else {
                av = make_float4(0.f, 0.f, 0.f, 0.f); hv = av;
            }
            ((float4*)(rb + r * 256))[lane] = av;
            ((float4*)(rb + r * 256 + 128))[lane] = hv;
        }
        __syncwarp();

        unsigned long long acc[4];
        #pragma unroll
        for (int r = 0; r < 4; r++) acc[r] = bvp;

        #pragma unroll 4
        for (int k = 0; k < 256; k++) {
            unsigned long long w = Wcp[k * 32 + lane];
            #pragma unroll
            for (int r = 0; r < 4; r++) {
                unsigned long long aa = pack_dup(rb[r * 256 + k]);
                ffma2(acc[r], aa, w);
            }
        }

        #pragma unroll
        for (int r = 0; r < 4; r++) {
            int row = base + r;
            if (row >= N) continue;                    // uniform across warp
            float2 av = unpack2(acc[r]);
            float v0 = av.x, v1 = av.y;
            float m = fmaxf(v0, v1);
            #pragma unroll
            for (int o = 16; o; o >>= 1) m = fmaxf(m, __shfl_xor_sync(0xffffffffu, m, o));
            float e0 = __expf(v0 - m), e1 = __expf(v1 - m);
            float ssum = e0 + e1;
            #pragma unroll
            for (int o = 16; o; o >>= 1) ssum += __shfl_xor_sync(0xffffffffu, ssum, o);
            float inv = 1.0f / ssum;
            sw[lane * 2]     = e0 * inv;
            sw[lane * 2 + 1] = e1 * inv;
            __syncwarp();

            unsigned long long a2 = 0;   // (0.f, 0.f)
            #pragma unroll 4
            for (int k = 0; k < 64; k++) {
                unsigned long long ss = pack_dup(sw[k]);
                ffma2(a2, ss, Wgp[k * 32 + lane]);
            }
            __syncwarp();

            float2 xwv = unpack2(a2);
            float dv = g_dinv[row];
            ((float2*)(g_xw + (size_t)row * 64))[lane] = xwv;
            float d2 = dv * dv;
            float2 o2 = make_float2(xwv.x * d2 + bgv.x, xwv.y * d2 + bgv.y);
            ((float2*)(out + (size_t)row * 64))[lane] = o2;
        }
    }
}

// ---------------- GCN: warp-per-node gather, non-atomic accumulate into out ----------------
__global__ void gcn_gather_kernel(float* __restrict__ out, int N) {
    int node = (blockIdx.x * blockDim.x + threadIdx.x) >> 5;
    int lane = threadIdx.x & 31;
    if (node >= N) return;
    int start = g_rowptr[node], end = g_rowptr[node + 1];
    float2 a0 = make_float2(0.f, 0.f), a1 = make_float2(0.f, 0.f);
    float2 a2 = make_float2(0.f, 0.f), a3 = make_float2(0.f, 0.f);
    for (int eb = start; eb < end; eb += 32) {
        int m = end - eb; if (m > 32) m = 32;
        int sl = 0; float wl = 0.f;
        if (lane < m) { sl = g_csrc[eb + lane]; wl = g_dinv[sl]; }
        for (int k = 0; k < m; k += 4) {
            int   s0 = __shfl_sync(0xffffffffu, sl, k);
            float w0 = __shfl_sync(0xffffffffu, wl, k);
            float2 v0 = ((const float2*)(g_xw + (size_t)s0 * 64))[lane];
            a0.x += v0.x * w0; a0.y += v0.y * w0;
            if (k + 1 < m) {
                int   s1 = __shfl_sync(0xffffffffu, sl, k + 1);
                float w1 = __shfl_sync(0xffffffffu, wl, k + 1);
                float2 v1 = ((const float2*)(g_xw + (size_t)s1 * 64))[lane];
                a1.x += v1.x * w1; a1.y += v1.y * w1;
            }
            if (k + 2 < m) {
                int   s2 = __shfl_sync(0xffffffffu, sl, k + 2);
                float w2 = __shfl_sync(0xffffffffu, wl, k + 2);
                float2 v2 = ((const float2*)(g_xw + (size_t)s2 * 64))[lane];
                a2.x += v2.x * w2; a2.y += v2.y * w2;
            }
            if (k + 3 < m) {
                int   s3 = __shfl_sync(0xffffffffu, sl, k + 3);
                float w3 = __shfl_sync(0xffffffffu, wl, k + 3);
                float2 v3 = ((const float2*)(g_xw + (size_t)s3 * 64))[lane];
                a3.x += v3.x * w3; a3.y += v3.y * w3;
            }
        }
    }
    float di = g_dinv[node];
    float2* po = (float2*)(out + (size_t)node * 64) + lane;
    float2 cur = *po;
    cur.x += di * (a0.x + a1.x + a2.x + a3.x);
    cur.y += di * (a0.y + a1.y + a2.y + a3.y);
    *po = cur;
}

// ---------------- host launcher ----------------
extern "C" void kernel_launch(void* const* d_in, const int* in_sizes, int n_in,
                              void* d_out, int out_size) {
    const float* x   = (const float*)d_in[0];
    const void*  ei  = d_in[1];
    const float* W1l = (const float*)d_in[2];
    const float* b1l = (const float*)d_in[3];
    const float* W1r = (const float*)d_in[4];
    const float* W2l = (const float*)d_in[5];
    const float* b2l = (const float*)d_in[6];
    const float* W2r = (const float*)d_in[7];
    const float* Wg  = (const float*)d_in[8];
    const float* bg  = (const float*)d_in[9];
    float* out = (float*)d_out;

    int N = in_sizes[0] / 128;
    int E = in_sizes[1] / 2;

    void *p_deg, *p_fill, *p_flag;
    cudaGetSymbolAddress(&p_deg,  g_deg);
    cudaGetSymbolAddress(&p_fill, g_fill);
    cudaGetSymbolAddress(&p_flag, g_not64);

    cudaMemsetAsync(p_deg,  0, (size_t)N * sizeof(int));
    cudaMemsetAsync(p_fill, 0, (size_t)N * sizeof(int));
    cudaMemsetAsync(p_flag, 0, sizeof(int));

    // edge-index normalization (+degree histogram fused)
    int eb = (E + 255) / 256;
    detect_kernel<<<eb, 256>>>((const long long*)ei, E, N);
    convert_kernel<<<eb, 256>>>(ei, E);

    // CSR build (by dst)
    int nb = (N + SCAN_BS - 1) / SCAN_BS;
    scan_block_sums<<<nb, SCAN_BS>>>(N);
    scan_bsum<<<1, 128>>>(nb);
    scan_final<<<nb, SCAN_BS>>>(N, E);
    fill_kernel<<<eb, 256>>>(E);

    // SAGE1 (gather fused, FFMA2)
    cudaFuncSetAttribute(node1_kernel, cudaFuncAttributeMaxDynamicSharedMemorySize, 196608);
    node1_kernel<<<148, 512, 196608>>>(x, W1l, b1l, W1r, N);

    // SAGE2 (gather fused, FFMA2, +softmax +@Wg +self-loop init)
    cudaFuncSetAttribute(node2_kernel, cudaFuncAttributeMaxDynamicSharedMemorySize, 152064);
    node2_kernel<<<148, 512, 152064>>>(W2l, b2l, W2r, Wg, bg, out, N);

    // GCN edge accumulation (gather, non-atomic)
    int gb = (N * 32 + 255) / 256;
    gcn_gather_kernel<<<gb, 256>>>(out, N);
}